// round 1
// baseline (speedup 1.0000x reference)
#include <cuda_runtime.h>
#include <cuda_bf16.h>
#include <math.h>

// Problem constants
#define T_STEPS 100
#define BATCH   64
#define NINP    400
#define NHID    1150
#define G4      (4*NHID)       // 4600
#define NTOKEN  33278
#define MB      (T_STEPS*BATCH) // 6400 rows

// ---------------------------------------------------------------------------
// Scratch (static device allocations; allocation-free at runtime)
// ---------------------------------------------------------------------------
__device__ float g_x0 [MB * 2*NINP];      // [6400, 800]  embedded input
__device__ float g_xg [MB * G4];          // [6400, 4600] precomputed input gates (reused per layer)
__device__ float g_hs1[MB * NHID];        // [6400, 1150]
__device__ float g_hs2[MB * NHID];
__device__ float g_att[MB * NHID];
__device__ float g_h  [2 * BATCH * NHID]; // ping-pong
__device__ float g_c  [2 * BATCH * NHID];

// ---------------------------------------------------------------------------
// Embedding: x0[m, 0:400] = emb_W[input[m]], x0[m, 400:800] = emb_W[input2[m]]
// ---------------------------------------------------------------------------
__global__ void embed_kernel(const int* __restrict__ in1, const int* __restrict__ in2,
                             const float* __restrict__ embW, float* __restrict__ x0)
{
    int m = blockIdx.x;
    int i1 = in1[m];
    int i2 = in2[m];
    const float* e1 = embW + (size_t)i1 * NINP;
    const float* e2 = embW + (size_t)i2 * NINP;
    float* row = x0 + (size_t)m * (2*NINP);
    for (int k = threadIdx.x; k < NINP; k += blockDim.x) {
        row[k]        = e1[k];
        row[NINP + k] = e2[k];
    }
}

// ---------------------------------------------------------------------------
// Copy initial h/c into ping buffers
// ---------------------------------------------------------------------------
__global__ void copy2_kernel(const float* __restrict__ a, const float* __restrict__ b,
                             float* __restrict__ da, float* __restrict__ db, int n)
{
    int i = blockIdx.x * blockDim.x + threadIdx.x;
    if (i < n) { da[i] = a[i]; db[i] = b[i]; }
}

// ---------------------------------------------------------------------------
// Generic NT GEMM: C[m,n] = sum_k A[m*K+k]*B[n*K+k] (+ bias1[n] + bias2[n])
// Tile 128x64x8, thread tile 8x4, 256 threads.
// ---------------------------------------------------------------------------
__global__ __launch_bounds__(256)
void gemm_nt_kernel(const float* __restrict__ A, const float* __restrict__ B,
                    float* __restrict__ C, int M, int N, int K,
                    const float* __restrict__ bias1, const float* __restrict__ bias2)
{
    const int BM = 128, BN = 64, BK = 8, TM = 8, TN = 4;
    __shared__ float As[BK][BM + 4];
    __shared__ float Bs[BK][BN + 4];

    int m0 = blockIdx.y * BM;
    int n0 = blockIdx.x * BN;
    int tid = threadIdx.x;
    int tr = tid / 16;          // 0..15
    int tc = tid % 16;          // 0..15

    // loader mapping
    int aRow = tid / 2;         // 0..127
    int aK   = (tid % 2) * 4;   // 0 or 4
    int bRow = tid / 4;         // 0..63
    int bK   = (tid % 4) * 2;   // 0,2,4,6

    float acc[TM][TN];
    #pragma unroll
    for (int i = 0; i < TM; i++)
        #pragma unroll
        for (int j = 0; j < TN; j++) acc[i][j] = 0.f;

    const int mA = m0 + aRow;
    const int nB = n0 + bRow;

    for (int k0 = 0; k0 < K; k0 += BK) {
        #pragma unroll
        for (int i = 0; i < 4; i++) {
            int k = k0 + aK + i;
            As[aK + i][aRow] = (k < K && mA < M) ? A[(size_t)mA * K + k] : 0.f;
        }
        #pragma unroll
        for (int i = 0; i < 2; i++) {
            int k = k0 + bK + i;
            Bs[bK + i][bRow] = (k < K && nB < N) ? B[(size_t)nB * K + k] : 0.f;
        }
        __syncthreads();
        #pragma unroll
        for (int kk = 0; kk < BK; kk++) {
            float ra[TM], rb[TN];
            #pragma unroll
            for (int i = 0; i < TM; i++) ra[i] = As[kk][tr * TM + i];
            #pragma unroll
            for (int j = 0; j < TN; j++) rb[j] = Bs[kk][tc * TN + j];
            #pragma unroll
            for (int i = 0; i < TM; i++)
                #pragma unroll
                for (int j = 0; j < TN; j++)
                    acc[i][j] += ra[i] * rb[j];
        }
        __syncthreads();
    }

    #pragma unroll
    for (int i = 0; i < TM; i++) {
        int m = m0 + tr * TM + i;
        if (m >= M) continue;
        #pragma unroll
        for (int j = 0; j < TN; j++) {
            int n = n0 + tc * TN + j;
            if (n >= N) continue;
            float v = acc[i][j];
            if (bias1) v += bias1[n];
            if (bias2) v += bias2[n];
            C[(size_t)m * N + n] = v;
        }
    }
}

// ---------------------------------------------------------------------------
// Fused LSTM step: gates = Xg[t] + h_in @ Whh^T, then activations + c/h update.
// Gate columns interleaved: CTA handles 8 j's x 4 gates = 32 columns, all 64 rows.
// grid = ceil(1150/8) = 144 CTAs, 256 threads.
// Thread (trow 0..31, tcol 0..7): rows trow*2+{0,1}, one j (all 4 gates).
// ---------------------------------------------------------------------------
__global__ __launch_bounds__(256)
void lstm_step_kernel(const float* __restrict__ xg,    // [64, 4600] (biases folded in)
                      const float* __restrict__ Whh,   // [4600, 1150]
                      const float* __restrict__ h_in,  // [64, 1150]
                      const float* __restrict__ c_in,  // [64, 1150]
                      float* __restrict__ h_out,
                      float* __restrict__ c_out,
                      float* __restrict__ hs_out)      // [64, 1150] slice of hs[t]
{
    const int H = NHID;
    __shared__ float As[16][68];  // [k][b]
    __shared__ float Bs[16][36];  // [k][col], col = jl*4 + gate

    int j0   = blockIdx.x * 8;
    int tid  = threadIdx.x;
    int tcol = tid % 8;
    int trow = tid / 8;

    // loader mapping
    int aRow = tid / 4;          // 0..63
    int aK   = (tid % 4) * 4;
    int bCol = tid / 8;          // 0..31
    int bK   = (tid % 8) * 2;
    int jB   = j0 + bCol / 4;
    int gB   = bCol % 4;
    const float* wrow = (jB < H) ? (Whh + (size_t)(gB * H + jB) * H) : Whh;
    bool wvalid = (jB < H);

    float acc[2][4];
    #pragma unroll
    for (int r = 0; r < 2; r++)
        #pragma unroll
        for (int g = 0; g < 4; g++) acc[r][g] = 0.f;

    for (int k0 = 0; k0 < H; k0 += 16) {
        #pragma unroll
        for (int i = 0; i < 4; i++) {
            int k = k0 + aK + i;
            As[aK + i][aRow] = (k < H) ? h_in[aRow * H + k] : 0.f;
        }
        #pragma unroll
        for (int i = 0; i < 2; i++) {
            int k = k0 + bK + i;
            Bs[bK + i][bCol] = (wvalid && k < H) ? wrow[k] : 0.f;
        }
        __syncthreads();
        #pragma unroll
        for (int kk = 0; kk < 16; kk++) {
            float a0 = As[kk][trow * 2 + 0];
            float a1 = As[kk][trow * 2 + 1];
            float b0 = Bs[kk][tcol * 4 + 0];
            float b1 = Bs[kk][tcol * 4 + 1];
            float b2 = Bs[kk][tcol * 4 + 2];
            float b3 = Bs[kk][tcol * 4 + 3];
            acc[0][0] += a0 * b0; acc[0][1] += a0 * b1;
            acc[0][2] += a0 * b2; acc[0][3] += a0 * b3;
            acc[1][0] += a1 * b0; acc[1][1] += a1 * b1;
            acc[1][2] += a1 * b2; acc[1][3] += a1 * b3;
        }
        __syncthreads();
    }

    int j = j0 + tcol;
    if (j < H) {
        #pragma unroll
        for (int r = 0; r < 2; r++) {
            int b = trow * 2 + r;
            const float* x = xg + (size_t)b * G4;
            float vi = acc[r][0] + x[j];
            float vf = acc[r][1] + x[H + j];
            float vg = acc[r][2] + x[2 * H + j];
            float vo = acc[r][3] + x[3 * H + j];
            float ii = 1.f / (1.f + expf(-vi));
            float ff = 1.f / (1.f + expf(-vf));
            float gg = tanhf(vg);
            float oo = 1.f / (1.f + expf(-vo));
            float cn = ff * c_in[b * H + j] + ii * gg;
            float hn = oo * tanhf(cn);
            c_out[b * H + j] = cn;
            h_out[b * H + j] = hn;
            hs_out[b * H + j] = hn;
        }
    }
}

// ---------------------------------------------------------------------------
// Fused causal attention: one CTA per (b, t).
// scores[s] = <h_t, h_s> (s<=t); softmax; out[t,b,:] = sum_s attn[s] * h_s.
// ---------------------------------------------------------------------------
__global__ __launch_bounds__(128)
void attention_kernel(const float* __restrict__ hs, float* __restrict__ out)
{
    int b = blockIdx.x;
    int t = blockIdx.y;
    const int H = NHID;
    __shared__ float ht[NHID];
    __shared__ float sc[T_STEPS];
    __shared__ float red[128];
    int tid = threadIdx.x;

    const float* hsb = hs + (size_t)b * H;  // index by + s*BATCH*H

    for (int k = tid; k < H; k += 128)
        ht[k] = hsb[(size_t)t * BATCH * H + k];
    __syncthreads();

    float lmax = -1e30f;
    for (int s = tid; s <= t; s += 128) {
        const float* row = hsb + (size_t)s * BATCH * H;
        float d = 0.f;
        for (int k = 0; k < H; k++) d += ht[k] * row[k];
        sc[s] = d;
        lmax = fmaxf(lmax, d);
    }
    red[tid] = lmax;
    __syncthreads();
    #pragma unroll
    for (int off = 64; off > 0; off >>= 1) {
        if (tid < off) red[tid] = fmaxf(red[tid], red[tid + off]);
        __syncthreads();
    }
    float mx = red[0];
    __syncthreads();

    float lsum = 0.f;
    for (int s = tid; s <= t; s += 128) {
        float e = expf(sc[s] - mx);
        sc[s] = e;
        lsum += e;
    }
    red[tid] = lsum;
    __syncthreads();
    #pragma unroll
    for (int off = 64; off > 0; off >>= 1) {
        if (tid < off) red[tid] += red[tid + off];
        __syncthreads();
    }
    float inv = 1.f / red[0];
    __syncthreads();

    for (int h = tid; h < H; h += 128) {
        float a = 0.f;
        for (int s = 0; s <= t; s++)
            a += sc[s] * hsb[(size_t)s * BATCH * H + h];
        out[((size_t)t * BATCH + b) * H + h] = a * inv;
    }
}

// ---------------------------------------------------------------------------
// Launch
// ---------------------------------------------------------------------------
static float* sym_addr(const void* sym)
{
    void* p = nullptr;
    cudaGetSymbolAddress(&p, sym);
    return (float*)p;
}

extern "C" void kernel_launch(void* const* d_in, const int* in_sizes, int n_in,
                              void* d_out, int out_size)
{
    const int*   in1  = (const int*)d_in[0];
    const int*   in2  = (const int*)d_in[1];
    const float* hc0[6] = { (const float*)d_in[2], (const float*)d_in[3],
                            (const float*)d_in[4], (const float*)d_in[5],
                            (const float*)d_in[6], (const float*)d_in[7] };
    const float* embW = (const float*)d_in[8];
    const float* W_ih[3], *W_hh[3], *b_ih[3], *b_hh[3];
    for (int l = 0; l < 3; l++) {
        W_ih[l] = (const float*)d_in[9  + 4*l];
        W_hh[l] = (const float*)d_in[10 + 4*l];
        b_ih[l] = (const float*)d_in[11 + 4*l];
        b_hh[l] = (const float*)d_in[12 + 4*l];
    }
    const float* decW = (const float*)d_in[21];
    const float* decb = (const float*)d_in[22];
    float* out = (float*)d_out;

    float* x0  = sym_addr(g_x0);
    float* xg  = sym_addr(g_xg);
    float* hs1 = sym_addr(g_hs1);
    float* hs2 = sym_addr(g_hs2);
    float* att = sym_addr(g_att);
    float* hbuf = sym_addr(g_h);
    float* cbuf = sym_addr(g_c);
    const int HC = BATCH * NHID; // 73600

    // 1. Embedding
    embed_kernel<<<MB, 256>>>(in1, in2, embW, x0);

    const float* layer_in[3]  = { x0, hs1, hs2 };
    const int    layer_K[3]   = { 2*NINP, NHID, NHID };
    float*       layer_out[3] = { hs1, hs2, hs1 };

    for (int l = 0; l < 3; l++) {
        // 2. Input gates for all timesteps: Xg = X @ W_ih^T + b_ih + b_hh
        dim3 grid((G4 + 63) / 64, (MB + 127) / 128);
        gemm_nt_kernel<<<grid, 256>>>(layer_in[l], W_ih[l], xg,
                                      MB, G4, layer_K[l], b_ih[l], b_hh[l]);
        // 3. init h/c ping buffers
        copy2_kernel<<<(HC + 255) / 256, 256>>>(hc0[2*l], hc0[2*l + 1],
                                                hbuf, cbuf, HC);
        // 4. sequential recurrence
        for (int t = 0; t < T_STEPS; t++) {
            float* h_in  = hbuf + (t & 1) * HC;
            float* c_in  = cbuf + (t & 1) * HC;
            float* h_out = hbuf + ((t + 1) & 1) * HC;
            float* c_out = cbuf + ((t + 1) & 1) * HC;
            lstm_step_kernel<<<(NHID + 7) / 8, 256>>>(
                xg + (size_t)t * BATCH * G4, W_hh[l],
                h_in, c_in, h_out, c_out,
                layer_out[l] + (size_t)t * BATCH * NHID);
        }
    }

    // 5. Causal attention over last layer's hidden states (in hs1)
    attention_kernel<<<dim3(BATCH, T_STEPS), 128>>>(hs1, att);

    // 6. Decoder: out = att.reshape(6400,1150) @ dec_W^T + dec_b
    dim3 dgrid((NTOKEN + 63) / 64, (MB + 127) / 128);
    gemm_nt_kernel<<<dgrid, 256>>>(att, decW, out, MB, NTOKEN, NHID, decb, nullptr);
}